// round 10
// baseline (speedup 1.0000x reference)
#include <cuda_runtime.h>
#include <cuda_fp16.h>
#include <math.h>

// ---------------- problem constants ----------------
#define NCAM 6
#define CCH  256
#define NG   4
#define NP   8
#define NL   4
#define NQ   2500
#define CG   64

// Transposed fp16 feature buffer: per level l, layout [n][s=(y*W+x)][c],
// levels concatenated. Element offsets (in halves):
//  L0: 64x176 HW=11264  base 0
//  L1: 32x88  HW=2816   base 17301504
//  L2: 16x44  HW=704    base 21626880
//  L3: 8x22   HW=176    base 22708224
#define FEATT_TOTAL 22978560

__device__ __half  g_featT[FEATT_TOTAL];
__device__ float2  g_uv[NQ * NG * NP * NCAM];   // u=-1 sentinel if invalid
__device__ float   g_sw[NQ * NG * NP * NL];     // softmaxed scale weights

__device__ __forceinline__ unsigned int pack_half2(float lo, float hi)
{
    __half2 h = __floats2half2_rn(lo, hi);
    return *reinterpret_cast<unsigned int*>(&h);
}

// ---------------------------------------------------------------------------
// Fused kernel 1: prep (blocks 0..624) + transpose (blocks 625..2028).
// Independent work; prep's ALU/SHFL load hides under transpose's DRAM stalls.
// ---------------------------------------------------------------------------

#define PREP_BLOCKS 625
#define TOTAL_BLOCKS (PREP_BLOCKS + 1404)

__device__ __forceinline__ void do_transpose(
    int bid, unsigned int (*tile)[128],
    const float* __restrict__ f0, const float* __restrict__ f1,
    const float* __restrict__ f2, const float* __restrict__ f3)
{
    int lvl, local;
    if      (bid < 1056) { lvl = 0; local = bid;        }
    else if (bid < 1320) { lvl = 1; local = bid - 1056; }
    else if (bid < 1386) { lvl = 2; local = bid - 1320; }
    else                 { lvl = 3; local = bid - 1386; }

    const int   HWs[4]   = {11264, 2816, 704, 176};
    const int   TILES[4] = {176, 44, 11, 3};
    const int   BASE[4]  = {0, 17301504, 21626880, 22708224};
    const float* SRC[4]  = {f0, f1, f2, f3};

    const int HW = HWs[lvl];
    const int n  = local / TILES[lvl];
    const int tl = local % TILES[lvl];
    const int s0 = tl * 64;

    const int t     = threadIdx.x;
    const int lane  = t & 31;
    const int warp  = t >> 5;
    const int squad = lane & 7;     // 8 spatial quads of 4
    const int c2loc = lane >> 3;    // 0..3

    const float* srcn = SRC[lvl] + (size_t)n * CCH * HW;

    #pragma unroll
    for (int r = 0; r < 8; ++r) {
        int sblk = r & 1, cblk = r >> 1;
        int sl = sblk * 32 + squad * 4;        // 0..60, multiple of 4
        int s  = s0 + sl;
        int c2 = cblk * 32 + warp * 4 + c2loc; // 0..127
        if (s < HW) {                          // HW % 4 == 0 -> quad valid
            const float* pa = srcn + (size_t)(c2 * 2) * HW + s;
            float4 a = *(const float4*)pa;
            float4 b = *(const float4*)(pa + HW);
            int swz = ((sl >> 2) & 7) << 2;    // conflict-free XOR swizzle
            int cc  = c2 ^ swz;
            tile[sl + 0][cc] = pack_half2(a.x, b.x);
            tile[sl + 1][cc] = pack_half2(a.y, b.y);
            tile[sl + 2][cc] = pack_half2(a.z, b.z);
            tile[sl + 3][cc] = pack_half2(a.w, b.w);
        }
    }
    __syncthreads();

    __half* dstn = g_featT + BASE[lvl] + (size_t)n * HW * CCH;
    #pragma unroll
    for (int pass = 0; pass < 8; ++pass) {
        int sl = pass * 8 + warp;              // 0..63
        int ss = s0 + sl;
        if (ss < HW) {
            int swz = ((sl >> 2) & 7) << 2;
            unsigned int v0 = tile[sl][((lane << 2) + 0) ^ swz];
            unsigned int v1 = tile[sl][((lane << 2) + 1) ^ swz];
            unsigned int v2 = tile[sl][((lane << 2) + 2) ^ swz];
            unsigned int v3 = tile[sl][((lane << 2) + 3) ^ swz];
            uint4 v = make_uint4(v0, v1, v2, v3);
            *(uint4*)(dstn + (size_t)ss * CCH + lane * 8) = v;
        }
    }
}

__device__ __forceinline__ void do_prep(
    int bid, float* qcol /*[4][CCH]*/, float* res /*[4][224]*/,
    const float* __restrict__ query, const float* __restrict__ refpts,
    const float* __restrict__ l2i,
    const float* __restrict__ w_off, const float* __restrict__ b_off,
    const float* __restrict__ w_sw,  const float* __restrict__ b_sw)
{
    const int t  = threadIdx.x;
    const int q0 = bid * 4;

    for (int i = t; i < 4 * CCH; i += 256) {
        int c = i >> 2, qi = i & 3;
        qcol[qi * CCH + c] = query[c * NQ + q0 + qi];
    }
    __syncthreads();

    const int warp = t >> 5, lane = t & 31;
    for (int j = 0; j < 28; ++j) {
        int k = warp + (j << 3);
        const float* wrow; float bias;
        if (k < 96) { wrow = w_off + k * CCH;        bias = b_off[k];     }
        else        { wrow = w_sw  + (k - 96) * CCH; bias = b_sw[k - 96]; }
        float4 wa = ((const float4*)wrow)[lane];
        float4 wb = ((const float4*)wrow)[lane + 32];
        #pragma unroll
        for (int qi = 0; qi < 4; ++qi) {
            const float4* qv = (const float4*)(qcol + qi * CCH);
            float4 qa = qv[lane], qb = qv[lane + 32];
            float pv = wa.x*qa.x + wa.y*qa.y + wa.z*qa.z + wa.w*qa.w
                     + wb.x*qb.x + wb.y*qb.y + wb.z*qb.z + wb.w*qb.w;
            #pragma unroll
            for (int o = 16; o > 0; o >>= 1)
                pv += __shfl_xor_sync(0xffffffffu, pv, o);
            if (lane == 0) res[qi * 224 + k] = pv + bias;
        }
    }
    __syncthreads();

    if (t < 128) {
        const int qi = t >> 5, gp = t & 31;
        const int g = gp >> 3, p = gp & 7, p1 = p >> 1, p2 = p & 1;
        const int q = q0 + qi;

        const float lo[3]   = {-51.2f, -51.2f, -5.0f};
        const float span[3] = {102.4f, 102.4f, 8.0f};

        const int offk = ((g * 4 + p1) * 2 + p2) * 3;
        float pt[3];
        #pragma unroll
        for (int d = 0; d < 3; ++d) {
            float v  = res[qi * 224 + offk + d];
            float sg = 1.0f / (1.0f + expf(-v));
            float rp = refpts[(p1 * NQ + q) * 3 + d];
            pt[d] = rp * span[d] + lo[d] + (sg - 0.5f);
        }

        const int swk = 96 + gp * 4;
        float s0 = res[qi*224 + swk],   s1 = res[qi*224 + swk+1];
        float s2 = res[qi*224 + swk+2], s3 = res[qi*224 + swk+3];
        float m  = fmaxf(fmaxf(s0, s1), fmaxf(s2, s3));
        float e0 = expf(s0 - m), e1 = expf(s1 - m), e2 = expf(s2 - m), e3 = expf(s3 - m);
        float inv = 1.0f / (e0 + e1 + e2 + e3);
        const int idx = q * 32 + gp;
        g_sw[idx*4 + 0] = e0 * inv;
        g_sw[idx*4 + 1] = e1 * inv;
        g_sw[idx*4 + 2] = e2 * inv;
        g_sw[idx*4 + 3] = e3 * inv;

        #pragma unroll
        for (int n = 0; n < NCAM; ++n) {
            const float* M = l2i + n * 16;
            float cx = M[0]*pt[0] + M[1]*pt[1] + M[2]*pt[2]  + M[3];
            float cy = M[4]*pt[0] + M[5]*pt[1] + M[6]*pt[2]  + M[7];
            float cz = M[8]*pt[0] + M[9]*pt[1] + M[10]*pt[2] + M[11];
            float zc = fmaxf(cz, 1e-5f);
            float u  = cx / zc / 1408.0f;
            float v  = cy / zc / 512.0f;
            bool valid = (cz > 1e-5f) && (u > 0.0f) && (u < 1.0f)
                                      && (v > 0.0f) && (v < 1.0f);
            g_uv[idx * NCAM + n] = valid ? make_float2(u, v)
                                         : make_float2(-1.0f, -1.0f);
        }
    }
}

__global__ __launch_bounds__(256) void fused_tp_prep_kernel(
    const float* __restrict__ f0, const float* __restrict__ f1,
    const float* __restrict__ f2, const float* __restrict__ f3,
    const float* __restrict__ query, const float* __restrict__ refpts,
    const float* __restrict__ l2i,
    const float* __restrict__ w_off, const float* __restrict__ b_off,
    const float* __restrict__ w_sw,  const float* __restrict__ b_sw)
{
    __shared__ unsigned int tile[64][128];   // 32 KB, reused by both paths

    int bid = blockIdx.x;
    if (bid < PREP_BLOCKS) {
        float* qcol = (float*)tile;           // 4*256 floats
        float* res  = (float*)tile + 4 * CCH; // 4*224 floats
        do_prep(bid, qcol, res, query, refpts, l2i, w_off, b_off, w_sw, b_sw);
    } else {
        do_transpose(bid - PREP_BLOCKS, tile, f0, f1, f2, f3);
    }
}

// ---------------------------------------------------------------------------
// Kernel 2: gather + weighted accumulate, fp16 features, 2 channels/thread.
// Block = (q, g); 256 threads: p = tid>>5, lane = tid&31 -> channels 2l,2l+1.
// All 6 uv pairs + 4 scale weights loaded up-front (one L2 round-trip),
// validity bitmask, then only valid cams are processed.
// ---------------------------------------------------------------------------
__device__ __forceinline__ float2 sample_lvl2(const __half* __restrict__ fb,
                                              float u, float v, int W, int H)
{
    float x  = u * (float)W - 0.5f;
    float y  = v * (float)H - 0.5f;
    float xf = floorf(x), yf = floorf(y);
    float wx = x - xf,    wy = y - yf;
    int x0 = (int)xf, y0 = (int)yf;

    float2 v00 = {0.f,0.f}, v10 = {0.f,0.f}, v01 = {0.f,0.f}, v11 = {0.f,0.f};
    bool x0ok = ((unsigned)x0       < (unsigned)W);
    bool x1ok = ((unsigned)(x0 + 1) < (unsigned)W);
    bool y0ok = ((unsigned)y0       < (unsigned)H);
    bool y1ok = ((unsigned)(y0 + 1) < (unsigned)H);

    if (y0ok) {
        const __half* r = fb + (size_t)(y0 * W) * CCH;
        if (x0ok) v00 = __half22float2(*(const __half2*)(r + (size_t)x0 * CCH));
        if (x1ok) v10 = __half22float2(*(const __half2*)(r + (size_t)(x0+1) * CCH));
    }
    if (y1ok) {
        const __half* r = fb + (size_t)((y0 + 1) * W) * CCH;
        if (x0ok) v01 = __half22float2(*(const __half2*)(r + (size_t)x0 * CCH));
        if (x1ok) v11 = __half22float2(*(const __half2*)(r + (size_t)(x0+1) * CCH));
    }
    float w00 = (1.f - wx) * (1.f - wy);
    float w10 = wx * (1.f - wy);
    float w01 = (1.f - wx) * wy;
    float w11 = wx * wy;
    float2 r;
    r.x = v00.x*w00 + v10.x*w10 + v01.x*w01 + v11.x*w11;
    r.y = v00.y*w00 + v10.y*w10 + v01.y*w01 + v11.y*w11;
    return r;
}

__global__ __launch_bounds__(256) void gather_kernel(float* __restrict__ out)
{
    const int qg = blockIdx.x;          // 0..9999
    const int q  = qg >> 2, g = qg & 3;
    const int t  = threadIdx.x;
    const int p  = t >> 5, lane = t & 31;
    const int gp = (g << 3) | p;
    const int idx = q * 32 + gp;
    const int gc  = (g << 6) | (lane << 1);   // channel in [0,256), even

    // batch all per-point metadata loads: one L2 round-trip
    const float4 swv = *(const float4*)&g_sw[idx * 4];
    float2 uvr[NCAM];
    unsigned mask = 0;
    #pragma unroll
    for (int n = 0; n < NCAM; ++n) {
        uvr[n] = g_uv[idx * NCAM + n];
        if (uvr[n].x >= 0.0f) mask |= (1u << n);
    }

    float2 acc = {0.f, 0.f};
    #pragma unroll 1
    for (int n = 0; n < NCAM; ++n) {
        if (!(mask & (1u << n))) continue;
        const float u = uvr[n].x, v = uvr[n].y;
        const __half* fb;
        float2 s;
        fb = g_featT + 0        + (size_t)(n * 11264) * CCH + gc;
        s = sample_lvl2(fb, u, v, 176, 64);
        acc.x += swv.x * s.x; acc.y += swv.x * s.y;
        fb = g_featT + 17301504 + (size_t)(n * 2816)  * CCH + gc;
        s = sample_lvl2(fb, u, v, 88, 32);
        acc.x += swv.y * s.x; acc.y += swv.y * s.y;
        fb = g_featT + 21626880 + (size_t)(n * 704)   * CCH + gc;
        s = sample_lvl2(fb, u, v, 44, 16);
        acc.x += swv.z * s.x; acc.y += swv.z * s.y;
        fb = g_featT + 22708224 + (size_t)(n * 176)   * CCH + gc;
        s = sample_lvl2(fb, u, v, 22, 8);
        acc.x += swv.w * s.x; acc.y += swv.w * s.y;
    }
    // out layout [B,Q,G,P,CG]: (idx)*64 + cg ; write 2 channels at once
    *(float2*)(out + (size_t)idx * CG + (lane << 1)) = acc;
}

// ---------------------------------------------------------------------------
extern "C" void kernel_launch(void* const* d_in, const int* in_sizes, int n_in,
                              void* d_out, int out_size)
{
    const float* query  = (const float*)d_in[0];
    const float* refpts = (const float*)d_in[1];
    const float* l2i    = (const float*)d_in[2];
    const float* w_off  = (const float*)d_in[3];
    const float* b_off  = (const float*)d_in[4];
    const float* w_sw   = (const float*)d_in[5];
    const float* b_sw   = (const float*)d_in[6];
    const float* f0     = (const float*)d_in[7];
    const float* f1     = (const float*)d_in[8];
    const float* f2     = (const float*)d_in[9];
    const float* f3     = (const float*)d_in[10];
    float* out = (float*)d_out;

    fused_tp_prep_kernel<<<TOTAL_BLOCKS, 256>>>(f0, f1, f2, f3,
        query, refpts, l2i, w_off, b_off, w_sw, b_sw);
    gather_kernel<<<10000, 256>>>(out);
}

// round 11
// speedup vs baseline: 1.0026x; 1.0026x over previous
#include <cuda_runtime.h>
#include <cuda_fp16.h>
#include <math.h>

// ---------------- problem constants ----------------
#define NCAM 6
#define CCH  256
#define NG   4
#define NP   8
#define NL   4
#define NQ   2500
#define CG   64

// Transposed fp16 feature buffer: per level l, layout [n][s=(y*W+x)][c],
// levels concatenated. Element offsets (in halves):
//  L0: 64x176 HW=11264  base 0
//  L1: 32x88  HW=2816   base 17301504
//  L2: 16x44  HW=704    base 21626880
//  L3: 8x22   HW=176    base 22708224
#define FEATT_TOTAL 22978560

__device__ __half  g_featT[FEATT_TOTAL];
__device__ float2  g_uv[NQ * NG * NP * NCAM];   // u=-1 sentinel if invalid
__device__ float   g_sw[NQ * NG * NP * NL];     // softmaxed scale weights

__device__ __forceinline__ unsigned int pack_half2(float lo, float hi)
{
    __half2 h = __floats2half2_rn(lo, hi);
    return *reinterpret_cast<unsigned int*>(&h);
}

// ---------------------------------------------------------------------------
// Fused kernel 1: prep (blocks 0..624) + transpose (blocks 625..2028).
// Independent work; prep's ALU/SHFL load hides under transpose's DRAM stalls.
// ---------------------------------------------------------------------------

#define PREP_BLOCKS 625
#define TOTAL_BLOCKS (PREP_BLOCKS + 1404)

__device__ __forceinline__ void do_transpose(
    int bid, unsigned int (*tile)[128],
    const float* __restrict__ f0, const float* __restrict__ f1,
    const float* __restrict__ f2, const float* __restrict__ f3)
{
    int lvl, local;
    if      (bid < 1056) { lvl = 0; local = bid;        }
    else if (bid < 1320) { lvl = 1; local = bid - 1056; }
    else if (bid < 1386) { lvl = 2; local = bid - 1320; }
    else                 { lvl = 3; local = bid - 1386; }

    const int   HWs[4]   = {11264, 2816, 704, 176};
    const int   TILES[4] = {176, 44, 11, 3};
    const int   BASE[4]  = {0, 17301504, 21626880, 22708224};
    const float* SRC[4]  = {f0, f1, f2, f3};

    const int HW = HWs[lvl];
    const int n  = local / TILES[lvl];
    const int tl = local % TILES[lvl];
    const int s0 = tl * 64;

    const int t     = threadIdx.x;
    const int lane  = t & 31;
    const int warp  = t >> 5;
    const int squad = lane & 7;     // 8 spatial quads of 4
    const int c2loc = lane >> 3;    // 0..3

    const float* srcn = SRC[lvl] + (size_t)n * CCH * HW;

    #pragma unroll
    for (int r = 0; r < 8; ++r) {
        int sblk = r & 1, cblk = r >> 1;
        int sl = sblk * 32 + squad * 4;        // 0..60, multiple of 4
        int s  = s0 + sl;
        int c2 = cblk * 32 + warp * 4 + c2loc; // 0..127
        if (s < HW) {                          // HW % 4 == 0 -> quad valid
            const float* pa = srcn + (size_t)(c2 * 2) * HW + s;
            float4 a = *(const float4*)pa;
            float4 b = *(const float4*)(pa + HW);
            int swz = ((sl >> 2) & 7) << 2;    // conflict-free XOR swizzle
            int cc  = c2 ^ swz;
            tile[sl + 0][cc] = pack_half2(a.x, b.x);
            tile[sl + 1][cc] = pack_half2(a.y, b.y);
            tile[sl + 2][cc] = pack_half2(a.z, b.z);
            tile[sl + 3][cc] = pack_half2(a.w, b.w);
        }
    }
    __syncthreads();

    __half* dstn = g_featT + BASE[lvl] + (size_t)n * HW * CCH;
    #pragma unroll
    for (int pass = 0; pass < 8; ++pass) {
        int sl = pass * 8 + warp;              // 0..63
        int ss = s0 + sl;
        if (ss < HW) {
            int swz = ((sl >> 2) & 7) << 2;
            unsigned int v0 = tile[sl][((lane << 2) + 0) ^ swz];
            unsigned int v1 = tile[sl][((lane << 2) + 1) ^ swz];
            unsigned int v2 = tile[sl][((lane << 2) + 2) ^ swz];
            unsigned int v3 = tile[sl][((lane << 2) + 3) ^ swz];
            uint4 v = make_uint4(v0, v1, v2, v3);
            *(uint4*)(dstn + (size_t)ss * CCH + lane * 8) = v;
        }
    }
}

__device__ __forceinline__ void do_prep(
    int bid, float* qcol /*[4][CCH]*/, float* res /*[4][224]*/,
    const float* __restrict__ query, const float* __restrict__ refpts,
    const float* __restrict__ l2i,
    const float* __restrict__ w_off, const float* __restrict__ b_off,
    const float* __restrict__ w_sw,  const float* __restrict__ b_sw)
{
    const int t  = threadIdx.x;
    const int q0 = bid * 4;

    for (int i = t; i < 4 * CCH; i += 256) {
        int c = i >> 2, qi = i & 3;
        qcol[qi * CCH + c] = query[c * NQ + q0 + qi];
    }
    __syncthreads();

    const int warp = t >> 5, lane = t & 31;
    for (int j = 0; j < 28; ++j) {
        int k = warp + (j << 3);
        const float* wrow; float bias;
        if (k < 96) { wrow = w_off + k * CCH;        bias = b_off[k];     }
        else        { wrow = w_sw  + (k - 96) * CCH; bias = b_sw[k - 96]; }
        float4 wa = ((const float4*)wrow)[lane];
        float4 wb = ((const float4*)wrow)[lane + 32];
        #pragma unroll
        for (int qi = 0; qi < 4; ++qi) {
            const float4* qv = (const float4*)(qcol + qi * CCH);
            float4 qa = qv[lane], qb = qv[lane + 32];
            float pv = wa.x*qa.x + wa.y*qa.y + wa.z*qa.z + wa.w*qa.w
                     + wb.x*qb.x + wb.y*qb.y + wb.z*qb.z + wb.w*qb.w;
            #pragma unroll
            for (int o = 16; o > 0; o >>= 1)
                pv += __shfl_xor_sync(0xffffffffu, pv, o);
            if (lane == 0) res[qi * 224 + k] = pv + bias;
        }
    }
    __syncthreads();

    if (t < 128) {
        const int qi = t >> 5, gp = t & 31;
        const int g = gp >> 3, p = gp & 7, p1 = p >> 1, p2 = p & 1;
        const int q = q0 + qi;

        const float lo[3]   = {-51.2f, -51.2f, -5.0f};
        const float span[3] = {102.4f, 102.4f, 8.0f};

        const int offk = ((g * 4 + p1) * 2 + p2) * 3;
        float pt[3];
        #pragma unroll
        for (int d = 0; d < 3; ++d) {
            float v  = res[qi * 224 + offk + d];
            float sg = 1.0f / (1.0f + expf(-v));
            float rp = refpts[(p1 * NQ + q) * 3 + d];
            pt[d] = rp * span[d] + lo[d] + (sg - 0.5f);
        }

        const int swk = 96 + gp * 4;
        float s0 = res[qi*224 + swk],   s1 = res[qi*224 + swk+1];
        float s2 = res[qi*224 + swk+2], s3 = res[qi*224 + swk+3];
        float m  = fmaxf(fmaxf(s0, s1), fmaxf(s2, s3));
        float e0 = expf(s0 - m), e1 = expf(s1 - m), e2 = expf(s2 - m), e3 = expf(s3 - m);
        float inv = 1.0f / (e0 + e1 + e2 + e3);
        const int idx = q * 32 + gp;
        g_sw[idx*4 + 0] = e0 * inv;
        g_sw[idx*4 + 1] = e1 * inv;
        g_sw[idx*4 + 2] = e2 * inv;
        g_sw[idx*4 + 3] = e3 * inv;

        #pragma unroll
        for (int n = 0; n < NCAM; ++n) {
            const float* M = l2i + n * 16;
            float cx = M[0]*pt[0] + M[1]*pt[1] + M[2]*pt[2]  + M[3];
            float cy = M[4]*pt[0] + M[5]*pt[1] + M[6]*pt[2]  + M[7];
            float cz = M[8]*pt[0] + M[9]*pt[1] + M[10]*pt[2] + M[11];
            float zc = fmaxf(cz, 1e-5f);
            float u  = cx / zc / 1408.0f;
            float v  = cy / zc / 512.0f;
            bool valid = (cz > 1e-5f) && (u > 0.0f) && (u < 1.0f)
                                      && (v > 0.0f) && (v < 1.0f);
            g_uv[idx * NCAM + n] = valid ? make_float2(u, v)
                                         : make_float2(-1.0f, -1.0f);
        }
    }
}

__global__ __launch_bounds__(256) void fused_tp_prep_kernel(
    const float* __restrict__ f0, const float* __restrict__ f1,
    const float* __restrict__ f2, const float* __restrict__ f3,
    const float* __restrict__ query, const float* __restrict__ refpts,
    const float* __restrict__ l2i,
    const float* __restrict__ w_off, const float* __restrict__ b_off,
    const float* __restrict__ w_sw,  const float* __restrict__ b_sw)
{
    __shared__ unsigned int tile[64][128];   // 32 KB, reused by both paths

    int bid = blockIdx.x;
    if (bid < PREP_BLOCKS) {
        float* qcol = (float*)tile;           // 4*256 floats
        float* res  = (float*)tile + 4 * CCH; // 4*224 floats
        do_prep(bid, qcol, res, query, refpts, l2i, w_off, b_off, w_sw, b_sw);
    } else {
        do_transpose(bid - PREP_BLOCKS, tile, f0, f1, f2, f3);
    }
}

// ---------------------------------------------------------------------------
// Kernel 2: gather + weighted accumulate, fp16 features, 2 channels/thread.
// Block = (q, g); 256 threads: p = tid>>5, lane = tid&31 -> channels 2l,2l+1.
// All 6 uv pairs + 4 scale weights loaded up-front (one L2 round-trip),
// validity bitmask, then only valid cams are processed.
// ---------------------------------------------------------------------------
__device__ __forceinline__ float2 sample_lvl2(const __half* __restrict__ fb,
                                              float u, float v, int W, int H)
{
    float x  = u * (float)W - 0.5f;
    float y  = v * (float)H - 0.5f;
    float xf = floorf(x), yf = floorf(y);
    float wx = x - xf,    wy = y - yf;
    int x0 = (int)xf, y0 = (int)yf;

    float2 v00 = {0.f,0.f}, v10 = {0.f,0.f}, v01 = {0.f,0.f}, v11 = {0.f,0.f};
    bool x0ok = ((unsigned)x0       < (unsigned)W);
    bool x1ok = ((unsigned)(x0 + 1) < (unsigned)W);
    bool y0ok = ((unsigned)y0       < (unsigned)H);
    bool y1ok = ((unsigned)(y0 + 1) < (unsigned)H);

    if (y0ok) {
        const __half* r = fb + (size_t)(y0 * W) * CCH;
        if (x0ok) v00 = __half22float2(*(const __half2*)(r + (size_t)x0 * CCH));
        if (x1ok) v10 = __half22float2(*(const __half2*)(r + (size_t)(x0+1) * CCH));
    }
    if (y1ok) {
        const __half* r = fb + (size_t)((y0 + 1) * W) * CCH;
        if (x0ok) v01 = __half22float2(*(const __half2*)(r + (size_t)x0 * CCH));
        if (x1ok) v11 = __half22float2(*(const __half2*)(r + (size_t)(x0+1) * CCH));
    }
    float w00 = (1.f - wx) * (1.f - wy);
    float w10 = wx * (1.f - wy);
    float w01 = (1.f - wx) * wy;
    float w11 = wx * wy;
    float2 r;
    r.x = v00.x*w00 + v10.x*w10 + v01.x*w01 + v11.x*w11;
    r.y = v00.y*w00 + v10.y*w10 + v01.y*w01 + v11.y*w11;
    return r;
}

__global__ __launch_bounds__(256) void gather_kernel(float* __restrict__ out)
{
    const int qg = blockIdx.x;          // 0..9999
    const int q  = qg >> 2, g = qg & 3;
    const int t  = threadIdx.x;
    const int p  = t >> 5, lane = t & 31;
    const int gp = (g << 3) | p;
    const int idx = q * 32 + gp;
    const int gc  = (g << 6) | (lane << 1);   // channel in [0,256), even

    // batch all per-point metadata loads: one L2 round-trip
    const float4 swv = *(const float4*)&g_sw[idx * 4];
    float2 uvr[NCAM];
    unsigned mask = 0;
    #pragma unroll
    for (int n = 0; n < NCAM; ++n) {
        uvr[n] = g_uv[idx * NCAM + n];
        if (uvr[n].x >= 0.0f) mask |= (1u << n);
    }

    float2 acc = {0.f, 0.f};
    #pragma unroll 1
    for (int n = 0; n < NCAM; ++n) {
        if (!(mask & (1u << n))) continue;
        const float u = uvr[n].x, v = uvr[n].y;
        const __half* fb;
        float2 s;
        fb = g_featT + 0        + (size_t)(n * 11264) * CCH + gc;
        s = sample_lvl2(fb, u, v, 176, 64);
        acc.x += swv.x * s.x; acc.y += swv.x * s.y;
        fb = g_featT + 17301504 + (size_t)(n * 2816)  * CCH + gc;
        s = sample_lvl2(fb, u, v, 88, 32);
        acc.x += swv.y * s.x; acc.y += swv.y * s.y;
        fb = g_featT + 21626880 + (size_t)(n * 704)   * CCH + gc;
        s = sample_lvl2(fb, u, v, 44, 16);
        acc.x += swv.z * s.x; acc.y += swv.z * s.y;
        fb = g_featT + 22708224 + (size_t)(n * 176)   * CCH + gc;
        s = sample_lvl2(fb, u, v, 22, 8);
        acc.x += swv.w * s.x; acc.y += swv.w * s.y;
    }
    // out layout [B,Q,G,P,CG]: (idx)*64 + cg ; write 2 channels at once
    *(float2*)(out + (size_t)idx * CG + (lane << 1)) = acc;
}

// ---------------------------------------------------------------------------
extern "C" void kernel_launch(void* const* d_in, const int* in_sizes, int n_in,
                              void* d_out, int out_size)
{
    const float* query  = (const float*)d_in[0];
    const float* refpts = (const float*)d_in[1];
    const float* l2i    = (const float*)d_in[2];
    const float* w_off  = (const float*)d_in[3];
    const float* b_off  = (const float*)d_in[4];
    const float* w_sw   = (const float*)d_in[5];
    const float* b_sw   = (const float*)d_in[6];
    const float* f0     = (const float*)d_in[7];
    const float* f1     = (const float*)d_in[8];
    const float* f2     = (const float*)d_in[9];
    const float* f3     = (const float*)d_in[10];
    float* out = (float*)d_out;

    fused_tp_prep_kernel<<<TOTAL_BLOCKS, 256>>>(f0, f1, f2, f3,
        query, refpts, l2i, w_off, b_off, w_sw, b_sw);
    gather_kernel<<<10000, 256>>>(out);
}

// round 12
// speedup vs baseline: 1.0030x; 1.0004x over previous
#include <cuda_runtime.h>
#include <cuda_fp16.h>
#include <math.h>

// ---------------- problem constants ----------------
#define NCAM 6
#define CCH  256
#define NG   4
#define NP   8
#define NL   4
#define NQ   2500
#define CG   64

// Transposed fp16 feature buffer: per level l, layout [n][s=(y*W+x)][c],
// levels concatenated. Element offsets (in halves):
//  L0: 64x176 HW=11264  base 0
//  L1: 32x88  HW=2816   base 17301504
//  L2: 16x44  HW=704    base 21626880
//  L3: 8x22   HW=176    base 22708224
#define FEATT_TOTAL 22978560

__device__ __half  g_featT[FEATT_TOTAL];
__device__ float2  g_uv[NQ * NG * NP * NCAM];   // u=-1 sentinel if invalid
__device__ float   g_sw[NQ * NG * NP * NL];     // softmaxed scale weights

__device__ __forceinline__ unsigned int pack_half2(float lo, float hi)
{
    __half2 h = __floats2half2_rn(lo, hi);
    return *reinterpret_cast<unsigned int*>(&h);
}

// ---------------------------------------------------------------------------
// Fused kernel 1: prep (blocks 0..624) + transpose (blocks 625..2028).
// Independent work; prep's ALU/SHFL load hides under transpose's DRAM stalls.
// ---------------------------------------------------------------------------

#define PREP_BLOCKS 625
#define TOTAL_BLOCKS (PREP_BLOCKS + 1404)

__device__ __forceinline__ void do_transpose(
    int bid, unsigned int (*tile)[128],
    const float* __restrict__ f0, const float* __restrict__ f1,
    const float* __restrict__ f2, const float* __restrict__ f3)
{
    int lvl, local;
    if      (bid < 1056) { lvl = 0; local = bid;        }
    else if (bid < 1320) { lvl = 1; local = bid - 1056; }
    else if (bid < 1386) { lvl = 2; local = bid - 1320; }
    else                 { lvl = 3; local = bid - 1386; }

    const int   HWs[4]   = {11264, 2816, 704, 176};
    const int   TILES[4] = {176, 44, 11, 3};
    const int   BASE[4]  = {0, 17301504, 21626880, 22708224};
    const float* SRC[4]  = {f0, f1, f2, f3};

    const int HW = HWs[lvl];
    const int n  = local / TILES[lvl];
    const int tl = local % TILES[lvl];
    const int s0 = tl * 64;

    const int t     = threadIdx.x;
    const int lane  = t & 31;
    const int warp  = t >> 5;
    const int squad = lane & 7;     // 8 spatial quads of 4
    const int c2loc = lane >> 3;    // 0..3

    const float* srcn = SRC[lvl] + (size_t)n * CCH * HW;

    #pragma unroll
    for (int r = 0; r < 8; ++r) {
        int sblk = r & 1, cblk = r >> 1;
        int sl = sblk * 32 + squad * 4;        // 0..60, multiple of 4
        int s  = s0 + sl;
        int c2 = cblk * 32 + warp * 4 + c2loc; // 0..127
        if (s < HW) {                          // HW % 4 == 0 -> quad valid
            const float* pa = srcn + (size_t)(c2 * 2) * HW + s;
            float4 a = *(const float4*)pa;
            float4 b = *(const float4*)(pa + HW);
            int swz = ((sl >> 2) & 7) << 2;    // conflict-free XOR swizzle
            int cc  = c2 ^ swz;
            tile[sl + 0][cc] = pack_half2(a.x, b.x);
            tile[sl + 1][cc] = pack_half2(a.y, b.y);
            tile[sl + 2][cc] = pack_half2(a.z, b.z);
            tile[sl + 3][cc] = pack_half2(a.w, b.w);
        }
    }
    __syncthreads();

    __half* dstn = g_featT + BASE[lvl] + (size_t)n * HW * CCH;
    #pragma unroll
    for (int pass = 0; pass < 8; ++pass) {
        int sl = pass * 8 + warp;              // 0..63
        int ss = s0 + sl;
        if (ss < HW) {
            int swz = ((sl >> 2) & 7) << 2;
            unsigned int v0 = tile[sl][((lane << 2) + 0) ^ swz];
            unsigned int v1 = tile[sl][((lane << 2) + 1) ^ swz];
            unsigned int v2 = tile[sl][((lane << 2) + 2) ^ swz];
            unsigned int v3 = tile[sl][((lane << 2) + 3) ^ swz];
            uint4 v = make_uint4(v0, v1, v2, v3);
            *(uint4*)(dstn + (size_t)ss * CCH + lane * 8) = v;
        }
    }
}

__device__ __forceinline__ void do_prep(
    int bid, float* qcol /*[4][CCH]*/, float* res /*[4][224]*/,
    const float* __restrict__ query, const float* __restrict__ refpts,
    const float* __restrict__ l2i,
    const float* __restrict__ w_off, const float* __restrict__ b_off,
    const float* __restrict__ w_sw,  const float* __restrict__ b_sw)
{
    const int t  = threadIdx.x;
    const int q0 = bid * 4;

    for (int i = t; i < 4 * CCH; i += 256) {
        int c = i >> 2, qi = i & 3;
        qcol[qi * CCH + c] = query[c * NQ + q0 + qi];
    }
    __syncthreads();

    const int warp = t >> 5, lane = t & 31;
    for (int j = 0; j < 28; ++j) {
        int k = warp + (j << 3);
        const float* wrow; float bias;
        if (k < 96) { wrow = w_off + k * CCH;        bias = b_off[k];     }
        else        { wrow = w_sw  + (k - 96) * CCH; bias = b_sw[k - 96]; }
        float4 wa = ((const float4*)wrow)[lane];
        float4 wb = ((const float4*)wrow)[lane + 32];
        #pragma unroll
        for (int qi = 0; qi < 4; ++qi) {
            const float4* qv = (const float4*)(qcol + qi * CCH);
            float4 qa = qv[lane], qb = qv[lane + 32];
            float pv = wa.x*qa.x + wa.y*qa.y + wa.z*qa.z + wa.w*qa.w
                     + wb.x*qb.x + wb.y*qb.y + wb.z*qb.z + wb.w*qb.w;
            #pragma unroll
            for (int o = 16; o > 0; o >>= 1)
                pv += __shfl_xor_sync(0xffffffffu, pv, o);
            if (lane == 0) res[qi * 224 + k] = pv + bias;
        }
    }
    __syncthreads();

    if (t < 128) {
        const int qi = t >> 5, gp = t & 31;
        const int g = gp >> 3, p = gp & 7, p1 = p >> 1, p2 = p & 1;
        const int q = q0 + qi;

        const float lo[3]   = {-51.2f, -51.2f, -5.0f};
        const float span[3] = {102.4f, 102.4f, 8.0f};

        const int offk = ((g * 4 + p1) * 2 + p2) * 3;
        float pt[3];
        #pragma unroll
        for (int d = 0; d < 3; ++d) {
            float v  = res[qi * 224 + offk + d];
            float sg = 1.0f / (1.0f + expf(-v));
            float rp = refpts[(p1 * NQ + q) * 3 + d];
            pt[d] = rp * span[d] + lo[d] + (sg - 0.5f);
        }

        const int swk = 96 + gp * 4;
        float s0 = res[qi*224 + swk],   s1 = res[qi*224 + swk+1];
        float s2 = res[qi*224 + swk+2], s3 = res[qi*224 + swk+3];
        float m  = fmaxf(fmaxf(s0, s1), fmaxf(s2, s3));
        float e0 = expf(s0 - m), e1 = expf(s1 - m), e2 = expf(s2 - m), e3 = expf(s3 - m);
        float inv = 1.0f / (e0 + e1 + e2 + e3);
        const int idx = q * 32 + gp;
        g_sw[idx*4 + 0] = e0 * inv;
        g_sw[idx*4 + 1] = e1 * inv;
        g_sw[idx*4 + 2] = e2 * inv;
        g_sw[idx*4 + 3] = e3 * inv;

        #pragma unroll
        for (int n = 0; n < NCAM; ++n) {
            const float* M = l2i + n * 16;
            float cx = M[0]*pt[0] + M[1]*pt[1] + M[2]*pt[2]  + M[3];
            float cy = M[4]*pt[0] + M[5]*pt[1] + M[6]*pt[2]  + M[7];
            float cz = M[8]*pt[0] + M[9]*pt[1] + M[10]*pt[2] + M[11];
            float zc = fmaxf(cz, 1e-5f);
            float u  = cx / zc / 1408.0f;
            float v  = cy / zc / 512.0f;
            bool valid = (cz > 1e-5f) && (u > 0.0f) && (u < 1.0f)
                                      && (v > 0.0f) && (v < 1.0f);
            g_uv[idx * NCAM + n] = valid ? make_float2(u, v)
                                         : make_float2(-1.0f, -1.0f);
        }
    }
}

__global__ __launch_bounds__(256) void fused_tp_prep_kernel(
    const float* __restrict__ f0, const float* __restrict__ f1,
    const float* __restrict__ f2, const float* __restrict__ f3,
    const float* __restrict__ query, const float* __restrict__ refpts,
    const float* __restrict__ l2i,
    const float* __restrict__ w_off, const float* __restrict__ b_off,
    const float* __restrict__ w_sw,  const float* __restrict__ b_sw)
{
    __shared__ unsigned int tile[64][128];   // 32 KB, reused by both paths

    int bid = blockIdx.x;
    if (bid < PREP_BLOCKS) {
        float* qcol = (float*)tile;           // 4*256 floats
        float* res  = (float*)tile + 4 * CCH; // 4*224 floats
        do_prep(bid, qcol, res, query, refpts, l2i, w_off, b_off, w_sw, b_sw);
    } else {
        do_transpose(bid - PREP_BLOCKS, tile, f0, f1, f2, f3);
    }
}

// ---------------------------------------------------------------------------
// Kernel 2: gather + weighted accumulate, fp16 features, 2 channels/thread.
// Block = (q, g); 256 threads: p = tid>>5, lane = tid&31 -> channels 2l,2l+1.
// All 6 uv pairs + 4 scale weights loaded up-front (one L2 round-trip),
// validity bitmask, then only valid cams are processed.
// ---------------------------------------------------------------------------
__device__ __forceinline__ float2 sample_lvl2(const __half* __restrict__ fb,
                                              float u, float v, int W, int H)
{
    float x  = u * (float)W - 0.5f;
    float y  = v * (float)H - 0.5f;
    float xf = floorf(x), yf = floorf(y);
    float wx = x - xf,    wy = y - yf;
    int x0 = (int)xf, y0 = (int)yf;

    float2 v00 = {0.f,0.f}, v10 = {0.f,0.f}, v01 = {0.f,0.f}, v11 = {0.f,0.f};
    bool x0ok = ((unsigned)x0       < (unsigned)W);
    bool x1ok = ((unsigned)(x0 + 1) < (unsigned)W);
    bool y0ok = ((unsigned)y0       < (unsigned)H);
    bool y1ok = ((unsigned)(y0 + 1) < (unsigned)H);

    if (y0ok) {
        const __half* r = fb + (size_t)(y0 * W) * CCH;
        if (x0ok) v00 = __half22float2(*(const __half2*)(r + (size_t)x0 * CCH));
        if (x1ok) v10 = __half22float2(*(const __half2*)(r + (size_t)(x0+1) * CCH));
    }
    if (y1ok) {
        const __half* r = fb + (size_t)((y0 + 1) * W) * CCH;
        if (x0ok) v01 = __half22float2(*(const __half2*)(r + (size_t)x0 * CCH));
        if (x1ok) v11 = __half22float2(*(const __half2*)(r + (size_t)(x0+1) * CCH));
    }
    float w00 = (1.f - wx) * (1.f - wy);
    float w10 = wx * (1.f - wy);
    float w01 = (1.f - wx) * wy;
    float w11 = wx * wy;
    float2 r;
    r.x = v00.x*w00 + v10.x*w10 + v01.x*w01 + v11.x*w11;
    r.y = v00.y*w00 + v10.y*w10 + v01.y*w01 + v11.y*w11;
    return r;
}

__global__ __launch_bounds__(256) void gather_kernel(float* __restrict__ out)
{
    const int qg = blockIdx.x;          // 0..9999
    const int q  = qg >> 2, g = qg & 3;
    const int t  = threadIdx.x;
    const int p  = t >> 5, lane = t & 31;
    const int gp = (g << 3) | p;
    const int idx = q * 32 + gp;
    const int gc  = (g << 6) | (lane << 1);   // channel in [0,256), even

    // batch all per-point metadata loads: one L2 round-trip
    const float4 swv = *(const float4*)&g_sw[idx * 4];
    float2 uvr[NCAM];
    unsigned mask = 0;
    #pragma unroll
    for (int n = 0; n < NCAM; ++n) {
        uvr[n] = g_uv[idx * NCAM + n];
        if (uvr[n].x >= 0.0f) mask |= (1u << n);
    }

    float2 acc = {0.f, 0.f};
    #pragma unroll 1
    for (int n = 0; n < NCAM; ++n) {
        if (!(mask & (1u << n))) continue;
        const float u = uvr[n].x, v = uvr[n].y;
        const __half* fb;
        float2 s;
        fb = g_featT + 0        + (size_t)(n * 11264) * CCH + gc;
        s = sample_lvl2(fb, u, v, 176, 64);
        acc.x += swv.x * s.x; acc.y += swv.x * s.y;
        fb = g_featT + 17301504 + (size_t)(n * 2816)  * CCH + gc;
        s = sample_lvl2(fb, u, v, 88, 32);
        acc.x += swv.y * s.x; acc.y += swv.y * s.y;
        fb = g_featT + 21626880 + (size_t)(n * 704)   * CCH + gc;
        s = sample_lvl2(fb, u, v, 44, 16);
        acc.x += swv.z * s.x; acc.y += swv.z * s.y;
        fb = g_featT + 22708224 + (size_t)(n * 176)   * CCH + gc;
        s = sample_lvl2(fb, u, v, 22, 8);
        acc.x += swv.w * s.x; acc.y += swv.w * s.y;
    }
    // out layout [B,Q,G,P,CG]: (idx)*64 + cg ; write 2 channels at once
    *(float2*)(out + (size_t)idx * CG + (lane << 1)) = acc;
}

// ---------------------------------------------------------------------------
extern "C" void kernel_launch(void* const* d_in, const int* in_sizes, int n_in,
                              void* d_out, int out_size)
{
    const float* query  = (const float*)d_in[0];
    const float* refpts = (const float*)d_in[1];
    const float* l2i    = (const float*)d_in[2];
    const float* w_off  = (const float*)d_in[3];
    const float* b_off  = (const float*)d_in[4];
    const float* w_sw   = (const float*)d_in[5];
    const float* b_sw   = (const float*)d_in[6];
    const float* f0     = (const float*)d_in[7];
    const float* f1     = (const float*)d_in[8];
    const float* f2     = (const float*)d_in[9];
    const float* f3     = (const float*)d_in[10];
    float* out = (float*)d_out;

    fused_tp_prep_kernel<<<TOTAL_BLOCKS, 256>>>(f0, f1, f2, f3,
        query, refpts, l2i, w_off, b_off, w_sw, b_sw);
    gather_kernel<<<10000, 256>>>(out);
}

// round 15
// speedup vs baseline: 1.1343x; 1.1309x over previous
#include <cuda_runtime.h>
#include <cuda_fp16.h>
#include <math.h>

// ---------------- problem constants ----------------
#define NCAM 6
#define CCH  256
#define NG   4
#define NP   8
#define NL   4
#define NQ   2500
#define CG   64
#define NIDX (NQ * NG * NP)     // 80000

// Transposed fp16 feature buffer: per level l, layout [n][s=(y*W+x)][c].
//  L0: 64x176 HW=11264  base 0
//  L1: 32x88  HW=2816   base 17301504
//  L2: 16x44  HW=704    base 21626880
//  L3: 8x22   HW=176    base 22708224
#define FEATT_TOTAL 22978560

__device__ __half  g_featT[FEATT_TOTAL];
// Sample descriptors: per (idx, cam, level) two float4:
//   [0] = {w00,w10,w01,w11} (bilinear x OOB x softmax-level weight, fp32)
//   [1] = {base, dx, dy, 0} as int bits (half-element offsets into g_featT)
__device__ float4  g_desc[NIDX * NCAM * NL * 2];    // 61.4 MB
__device__ int     g_mask[NIDX];                    // valid-cam bitmask

__device__ __forceinline__ unsigned int pack_half2(float lo, float hi)
{
    __half2 h = __floats2half2_rn(lo, hi);
    return *reinterpret_cast<unsigned int*>(&h);
}

// ---------------------------------------------------------------------------
// Fused kernel 1: prep+descriptors (blocks 0..624) + transpose (625..2028).
// ---------------------------------------------------------------------------
#define PREP_BLOCKS 625
#define TOTAL_BLOCKS (PREP_BLOCKS + 1404)

__device__ __forceinline__ void do_transpose(
    int bid, unsigned int (*tile)[128],
    const float* __restrict__ f0, const float* __restrict__ f1,
    const float* __restrict__ f2, const float* __restrict__ f3)
{
    int lvl, local;
    if      (bid < 1056) { lvl = 0; local = bid;        }
    else if (bid < 1320) { lvl = 1; local = bid - 1056; }
    else if (bid < 1386) { lvl = 2; local = bid - 1320; }
    else                 { lvl = 3; local = bid - 1386; }

    const int   HWs[4]   = {11264, 2816, 704, 176};
    const int   TILES[4] = {176, 44, 11, 3};
    const int   BASE[4]  = {0, 17301504, 21626880, 22708224};
    const float* SRC[4]  = {f0, f1, f2, f3};

    const int HW = HWs[lvl];
    const int n  = local / TILES[lvl];
    const int tl = local % TILES[lvl];
    const int s0 = tl * 64;

    const int t     = threadIdx.x;
    const int lane  = t & 31;
    const int warp  = t >> 5;
    const int squad = lane & 7;
    const int c2loc = lane >> 3;

    const float* srcn = SRC[lvl] + (size_t)n * CCH * HW;

    #pragma unroll
    for (int r = 0; r < 8; ++r) {
        int sblk = r & 1, cblk = r >> 1;
        int sl = sblk * 32 + squad * 4;
        int s  = s0 + sl;
        int c2 = cblk * 32 + warp * 4 + c2loc;
        if (s < HW) {
            const float* pa = srcn + (size_t)(c2 * 2) * HW + s;
            float4 a = *(const float4*)pa;
            float4 b = *(const float4*)(pa + HW);
            int swz = ((sl >> 2) & 7) << 2;
            int cc  = c2 ^ swz;
            tile[sl + 0][cc] = pack_half2(a.x, b.x);
            tile[sl + 1][cc] = pack_half2(a.y, b.y);
            tile[sl + 2][cc] = pack_half2(a.z, b.z);
            tile[sl + 3][cc] = pack_half2(a.w, b.w);
        }
    }
    __syncthreads();

    __half* dstn = g_featT + BASE[lvl] + (size_t)n * HW * CCH;
    #pragma unroll
    for (int pass = 0; pass < 8; ++pass) {
        int sl = pass * 8 + warp;
        int ss = s0 + sl;
        if (ss < HW) {
            int swz = ((sl >> 2) & 7) << 2;
            unsigned int v0 = tile[sl][((lane << 2) + 0) ^ swz];
            unsigned int v1 = tile[sl][((lane << 2) + 1) ^ swz];
            unsigned int v2 = tile[sl][((lane << 2) + 2) ^ swz];
            unsigned int v3 = tile[sl][((lane << 2) + 3) ^ swz];
            *(uint4*)(dstn + (size_t)ss * CCH + lane * 8) = make_uint4(v0, v1, v2, v3);
        }
    }
}

__device__ __forceinline__ void do_prep(
    int bid, float* sm,   // >= 4096 floats of shared scratch
    const float* __restrict__ query, const float* __restrict__ refpts,
    const float* __restrict__ l2i,
    const float* __restrict__ w_off, const float* __restrict__ b_off,
    const float* __restrict__ w_sw,  const float* __restrict__ b_sw)
{
    float*  qcol = sm;                    // 4*256
    float*  res  = sm + 1024;             // 4*224
    float2* suv  = (float2*)(sm + 2048);  // 128*6 float2 (1536 floats)
    float*  ssw  = sm + 3584;             // 128*4

    const int t  = threadIdx.x;
    const int q0 = bid * 4;

    for (int i = t; i < 4 * CCH; i += 256) {
        int c = i >> 2, qi = i & 3;
        qcol[qi * CCH + c] = query[c * NQ + q0 + qi];
    }
    __syncthreads();

    const int warp = t >> 5, lane = t & 31;
    for (int j = 0; j < 28; ++j) {
        int k = warp + (j << 3);
        const float* wrow; float bias;
        if (k < 96) { wrow = w_off + k * CCH;        bias = b_off[k];     }
        else        { wrow = w_sw  + (k - 96) * CCH; bias = b_sw[k - 96]; }
        float4 wa = ((const float4*)wrow)[lane];
        float4 wb = ((const float4*)wrow)[lane + 32];
        #pragma unroll
        for (int qi = 0; qi < 4; ++qi) {
            const float4* qv = (const float4*)(qcol + qi * CCH);
            float4 qa = qv[lane], qb = qv[lane + 32];
            float pv = wa.x*qa.x + wa.y*qa.y + wa.z*qa.z + wa.w*qa.w
                     + wb.x*qb.x + wb.y*qb.y + wb.z*qb.z + wb.w*qb.w;
            #pragma unroll
            for (int o = 16; o > 0; o >>= 1)
                pv += __shfl_xor_sync(0xffffffffu, pv, o);
            if (lane == 0) res[qi * 224 + k] = pv + bias;
        }
    }
    __syncthreads();

    if (t < 128) {
        const int qi = t >> 5, gp = t & 31;
        const int g = gp >> 3, p = gp & 7, p1 = p >> 1, p2 = p & 1;
        const int q = q0 + qi;

        const float lo[3]   = {-51.2f, -51.2f, -5.0f};
        const float span[3] = {102.4f, 102.4f, 8.0f};

        const int offk = ((g * 4 + p1) * 2 + p2) * 3;
        float pt[3];
        #pragma unroll
        for (int d = 0; d < 3; ++d) {
            float v  = res[qi * 224 + offk + d];
            float sg = 1.0f / (1.0f + expf(-v));
            float rp = refpts[(p1 * NQ + q) * 3 + d];
            pt[d] = rp * span[d] + lo[d] + (sg - 0.5f);
        }

        const int swk = 96 + gp * 4;
        float s0 = res[qi*224 + swk],   s1 = res[qi*224 + swk+1];
        float s2 = res[qi*224 + swk+2], s3 = res[qi*224 + swk+3];
        float m  = fmaxf(fmaxf(s0, s1), fmaxf(s2, s3));
        float e0 = expf(s0 - m), e1 = expf(s1 - m), e2 = expf(s2 - m), e3 = expf(s3 - m);
        float inv = 1.0f / (e0 + e1 + e2 + e3);
        const int sgp = qi * 32 + gp;
        ssw[sgp*4 + 0] = e0 * inv;
        ssw[sgp*4 + 1] = e1 * inv;
        ssw[sgp*4 + 2] = e2 * inv;
        ssw[sgp*4 + 3] = e3 * inv;

        int mask = 0;
        #pragma unroll
        for (int n = 0; n < NCAM; ++n) {
            const float* M = l2i + n * 16;
            float cx = M[0]*pt[0] + M[1]*pt[1] + M[2]*pt[2]  + M[3];
            float cy = M[4]*pt[0] + M[5]*pt[1] + M[6]*pt[2]  + M[7];
            float cz = M[8]*pt[0] + M[9]*pt[1] + M[10]*pt[2] + M[11];
            float zc = fmaxf(cz, 1e-5f);
            float u  = cx / zc / 1408.0f;
            float v  = cy / zc / 512.0f;
            bool valid = (cz > 1e-5f) && (u > 0.0f) && (u < 1.0f)
                                      && (v > 0.0f) && (v < 1.0f);
            if (valid) mask |= (1 << n);
            suv[sgp * NCAM + n] = valid ? make_float2(u, v)
                                        : make_float2(-1.0f, -1.0f);
        }
        g_mask[(q0 + qi) * 32 + gp] = mask;
    }
    __syncthreads();

    // ---- descriptor emission: 768 tasks = (qi, cam, gp), 3 per thread ----
    const int Wl[4]  = {176, 88, 44, 22};
    const int Hl[4]  = {64, 32, 16, 8};
    const int HWl[4] = {11264, 2816, 704, 176};
    const int LB[4]  = {0, 17301504, 21626880, 22708224};

    #pragma unroll
    for (int k = 0; k < 3; ++k) {
        int tau = t + (k << 8);          // 0..767
        int qi  = tau / 192;
        int r   = tau - qi * 192;
        int cam = r >> 5, gp = r & 31;
        int sgp = qi * 32 + gp;
        float2 uv = suv[sgp * NCAM + cam];
        if (uv.x < 0.0f) continue;
        int idx = (q0 + qi) * 32 + gp;
        float4* dst = g_desc + (size_t)(idx * NCAM + cam) * (NL * 2);

        #pragma unroll
        for (int l = 0; l < NL; ++l) {
            int W = Wl[l], H = Hl[l];
            float x = uv.x * (float)W - 0.5f;
            float y = uv.y * (float)H - 0.5f;
            float xf = floorf(x), yf = floorf(y);
            float wx = x - xf,    wy = y - yf;
            int x0 = (int)xf, y0 = (int)yf;
            int x0c = max(x0, 0);
            int x1c = min(x0 + 1, W - 1);
            int y0c = max(y0, 0);
            int y1c = min(y0 + 1, H - 1);
            float a = (x0 >= 0)     ? (1.0f - wx) : 0.0f;
            float b = (x0 + 1 <= W - 1) ? wx      : 0.0f;
            float c = (y0 >= 0)     ? (1.0f - wy) : 0.0f;
            float d = (y0 + 1 <= H - 1) ? wy      : 0.0f;
            float swl = ssw[sgp * 4 + l];
            float4 wv = make_float4(a*c*swl, b*c*swl, a*d*swl, b*d*swl);
            int base = LB[l] + cam * HWl[l] * CCH + (y0c * W + x0c) * CCH;
            int dx   = (x1c - x0c) * CCH;
            int dy   = (y1c - y0c) * W * CCH;
            float4 md = make_float4(__int_as_float(base), __int_as_float(dx),
                                    __int_as_float(dy), 0.0f);
            dst[l*2 + 0] = wv;
            dst[l*2 + 1] = md;
        }
    }
}

__global__ __launch_bounds__(256) void fused_tp_prep_kernel(
    const float* __restrict__ f0, const float* __restrict__ f1,
    const float* __restrict__ f2, const float* __restrict__ f3,
    const float* __restrict__ query, const float* __restrict__ refpts,
    const float* __restrict__ l2i,
    const float* __restrict__ w_off, const float* __restrict__ b_off,
    const float* __restrict__ w_sw,  const float* __restrict__ b_sw)
{
    __shared__ unsigned int tile[64][128];   // 32 KB, reused by both paths

    int bid = blockIdx.x;
    if (bid < PREP_BLOCKS) {
        do_prep(bid, (float*)tile, query, refpts, l2i, w_off, b_off, w_sw, b_sw);
    } else {
        do_transpose(bid - PREP_BLOCKS, tile, f0, f1, f2, f3);
    }
}

// ---------------------------------------------------------------------------
// Kernel 2: lean gather. Warp = one (q,g,p); lane = 2 channels.
// Per valid cam: 4 levels x (2 broadcast desc loads + 4 half2 loads + 8 FFMA).
// ---------------------------------------------------------------------------
__global__ __launch_bounds__(256) void gather_kernel(float* __restrict__ out)
{
    const int qg = blockIdx.x;          // 0..9999
    const int q  = qg >> 2, g = qg & 3;
    const int t  = threadIdx.x;
    const int p  = t >> 5, lane = t & 31;
    const int gp = (g << 3) | p;
    const int idx = q * 32 + gp;
    const int gc  = (g << 6) | (lane << 1);   // channel in [0,256), even

    int mask = g_mask[idx];
    float2 acc = {0.f, 0.f};

    while (mask) {
        int n = __ffs(mask) - 1;
        mask &= mask - 1;
        const float4* dp = g_desc + (size_t)(idx * NCAM + n) * (NL * 2);
        #pragma unroll
        for (int l = 0; l < NL; ++l) {
            float4 wv = dp[l*2 + 0];
            float4 md = dp[l*2 + 1];
            int b  = __float_as_int(md.x) + gc;
            int dx = __float_as_int(md.y);
            int dy = __float_as_int(md.z);
            float2 v00 = __half22float2(*(const __half2*)(g_featT + b));
            float2 v10 = __half22float2(*(const __half2*)(g_featT + b + dx));
            float2 v01 = __half22float2(*(const __half2*)(g_featT + b + dy));
            float2 v11 = __half22float2(*(const __half2*)(g_featT + b + dx + dy));
            acc.x += wv.x*v00.x + wv.y*v10.x + wv.z*v01.x + wv.w*v11.x;
            acc.y += wv.x*v00.y + wv.y*v10.y + wv.z*v01.y + wv.w*v11.y;
        }
    }
    // out layout [B,Q,G,P,CG]: (idx)*64 + cg
    *(float2*)(out + (size_t)idx * CG + (lane << 1)) = acc;
}

// ---------------------------------------------------------------------------
extern "C" void kernel_launch(void* const* d_in, const int* in_sizes, int n_in,
                              void* d_out, int out_size)
{
    const float* query  = (const float*)d_in[0];
    const float* refpts = (const float*)d_in[1];
    const float* l2i    = (const float*)d_in[2];
    const float* w_off  = (const float*)d_in[3];
    const float* b_off  = (const float*)d_in[4];
    const float* w_sw   = (const float*)d_in[5];
    const float* b_sw   = (const float*)d_in[6];
    const float* f0     = (const float*)d_in[7];
    const float* f1     = (const float*)d_in[8];
    const float* f2     = (const float*)d_in[9];
    const float* f3     = (const float*)d_in[10];
    float* out = (float*)d_out;

    fused_tp_prep_kernel<<<TOTAL_BLOCKS, 256>>>(f0, f1, f2, f3,
        query, refpts, l2i, w_off, b_off, w_sw, b_sw);
    gather_kernel<<<10000, 256>>>(out);
}

// round 17
// speedup vs baseline: 1.1409x; 1.0059x over previous
#include <cuda_runtime.h>
#include <cuda_fp16.h>
#include <math.h>

// ---------------- problem constants ----------------
#define NCAM 6
#define CCH  256
#define NG   4
#define NP   8
#define NL   4
#define NQ   2500
#define CG   64
#define NIDX (NQ * NG * NP)     // 80000

// Transposed fp16 feature buffer: per level l, layout [n][s=(y*W+x)][c].
//  L0: 64x176 HW=11264  base 0
//  L1: 32x88  HW=2816   base 17301504
//  L2: 16x44  HW=704    base 21626880
//  L3: 8x22   HW=176    base 22708224
#define FEATT_TOTAL 22978560

__device__ __half  g_featT[FEATT_TOTAL];
// Sample descriptors: per (idx, cam, level) two float4:
//   [0] = {w00,w10,w01,w11} (bilinear x OOB x softmax-level weight, fp32)
//   [1] = {base, dx, dy, 0} as int bits (half-element offsets into g_featT)
__device__ float4  g_desc[NIDX * NCAM * NL * 2];    // 61.4 MB
__device__ int     g_mask[NIDX];                    // valid-cam bitmask

__device__ __forceinline__ unsigned int pack_half2(float lo, float hi)
{
    __half2 h = __floats2half2_rn(lo, hi);
    return *reinterpret_cast<unsigned int*>(&h);
}

// ---------------------------------------------------------------------------
// Fused kernel 1: prep+descriptors (blocks 0..624) + transpose (625..2028).
// ---------------------------------------------------------------------------
#define PREP_BLOCKS 625
#define TOTAL_BLOCKS (PREP_BLOCKS + 1404)

__device__ __forceinline__ void do_transpose(
    int bid, unsigned int (*tile)[128],
    const float* __restrict__ f0, const float* __restrict__ f1,
    const float* __restrict__ f2, const float* __restrict__ f3)
{
    int lvl, local;
    if      (bid < 1056) { lvl = 0; local = bid;        }
    else if (bid < 1320) { lvl = 1; local = bid - 1056; }
    else if (bid < 1386) { lvl = 2; local = bid - 1320; }
    else                 { lvl = 3; local = bid - 1386; }

    const int   HWs[4]   = {11264, 2816, 704, 176};
    const int   TILES[4] = {176, 44, 11, 3};
    const int   BASE[4]  = {0, 17301504, 21626880, 22708224};
    const float* SRC[4]  = {f0, f1, f2, f3};

    const int HW = HWs[lvl];
    const int n  = local / TILES[lvl];
    const int tl = local % TILES[lvl];
    const int s0 = tl * 64;

    const int t     = threadIdx.x;
    const int lane  = t & 31;
    const int warp  = t >> 5;
    const int squad = lane & 7;
    const int c2loc = lane >> 3;

    const float* srcn = SRC[lvl] + (size_t)n * CCH * HW;

    #pragma unroll
    for (int r = 0; r < 8; ++r) {
        int sblk = r & 1, cblk = r >> 1;
        int sl = sblk * 32 + squad * 4;
        int s  = s0 + sl;
        int c2 = cblk * 32 + warp * 4 + c2loc;
        if (s < HW) {
            const float* pa = srcn + (size_t)(c2 * 2) * HW + s;
            float4 a = *(const float4*)pa;
            float4 b = *(const float4*)(pa + HW);
            int swz = ((sl >> 2) & 7) << 2;
            int cc  = c2 ^ swz;
            tile[sl + 0][cc] = pack_half2(a.x, b.x);
            tile[sl + 1][cc] = pack_half2(a.y, b.y);
            tile[sl + 2][cc] = pack_half2(a.z, b.z);
            tile[sl + 3][cc] = pack_half2(a.w, b.w);
        }
    }
    __syncthreads();

    __half* dstn = g_featT + BASE[lvl] + (size_t)n * HW * CCH;
    #pragma unroll
    for (int pass = 0; pass < 8; ++pass) {
        int sl = pass * 8 + warp;
        int ss = s0 + sl;
        if (ss < HW) {
            int swz = ((sl >> 2) & 7) << 2;
            unsigned int v0 = tile[sl][((lane << 2) + 0) ^ swz];
            unsigned int v1 = tile[sl][((lane << 2) + 1) ^ swz];
            unsigned int v2 = tile[sl][((lane << 2) + 2) ^ swz];
            unsigned int v3 = tile[sl][((lane << 2) + 3) ^ swz];
            *(uint4*)(dstn + (size_t)ss * CCH + lane * 8) = make_uint4(v0, v1, v2, v3);
        }
    }
}

__device__ __forceinline__ void do_prep(
    int bid, float* sm,   // >= 4096 floats of shared scratch
    const float* __restrict__ query, const float* __restrict__ refpts,
    const float* __restrict__ l2i,
    const float* __restrict__ w_off, const float* __restrict__ b_off,
    const float* __restrict__ w_sw,  const float* __restrict__ b_sw)
{
    float*  qcol = sm;                    // 4*256
    float*  res  = sm + 1024;             // 4*224
    float2* suv  = (float2*)(sm + 2048);  // 128*6 float2 (1536 floats)
    float*  ssw  = sm + 3584;             // 128*4

    const int t  = threadIdx.x;
    const int q0 = bid * 4;

    for (int i = t; i < 4 * CCH; i += 256) {
        int c = i >> 2, qi = i & 3;
        qcol[qi * CCH + c] = query[c * NQ + q0 + qi];
    }
    __syncthreads();

    const int warp = t >> 5, lane = t & 31;
    for (int j = 0; j < 28; ++j) {
        int k = warp + (j << 3);
        const float* wrow; float bias;
        if (k < 96) { wrow = w_off + k * CCH;        bias = b_off[k];     }
        else        { wrow = w_sw  + (k - 96) * CCH; bias = b_sw[k - 96]; }
        float4 wa = ((const float4*)wrow)[lane];
        float4 wb = ((const float4*)wrow)[lane + 32];
        #pragma unroll
        for (int qi = 0; qi < 4; ++qi) {
            const float4* qv = (const float4*)(qcol + qi * CCH);
            float4 qa = qv[lane], qb = qv[lane + 32];
            float pv = wa.x*qa.x + wa.y*qa.y + wa.z*qa.z + wa.w*qa.w
                     + wb.x*qb.x + wb.y*qb.y + wb.z*qb.z + wb.w*qb.w;
            #pragma unroll
            for (int o = 16; o > 0; o >>= 1)
                pv += __shfl_xor_sync(0xffffffffu, pv, o);
            if (lane == 0) res[qi * 224 + k] = pv + bias;
        }
    }
    __syncthreads();

    if (t < 128) {
        const int qi = t >> 5, gp = t & 31;
        const int g = gp >> 3, p = gp & 7, p1 = p >> 1, p2 = p & 1;
        const int q = q0 + qi;

        const float lo[3]   = {-51.2f, -51.2f, -5.0f};
        const float span[3] = {102.4f, 102.4f, 8.0f};

        const int offk = ((g * 4 + p1) * 2 + p2) * 3;
        float pt[3];
        #pragma unroll
        for (int d = 0; d < 3; ++d) {
            float v  = res[qi * 224 + offk + d];
            float sg = 1.0f / (1.0f + expf(-v));
            float rp = refpts[(p1 * NQ + q) * 3 + d];
            pt[d] = rp * span[d] + lo[d] + (sg - 0.5f);
        }

        const int swk = 96 + gp * 4;
        float s0 = res[qi*224 + swk],   s1 = res[qi*224 + swk+1];
        float s2 = res[qi*224 + swk+2], s3 = res[qi*224 + swk+3];
        float m  = fmaxf(fmaxf(s0, s1), fmaxf(s2, s3));
        float e0 = expf(s0 - m), e1 = expf(s1 - m), e2 = expf(s2 - m), e3 = expf(s3 - m);
        float inv = 1.0f / (e0 + e1 + e2 + e3);
        const int sgp = qi * 32 + gp;
        ssw[sgp*4 + 0] = e0 * inv;
        ssw[sgp*4 + 1] = e1 * inv;
        ssw[sgp*4 + 2] = e2 * inv;
        ssw[sgp*4 + 3] = e3 * inv;

        int mask = 0;
        #pragma unroll
        for (int n = 0; n < NCAM; ++n) {
            const float* M = l2i + n * 16;
            float cx = M[0]*pt[0] + M[1]*pt[1] + M[2]*pt[2]  + M[3];
            float cy = M[4]*pt[0] + M[5]*pt[1] + M[6]*pt[2]  + M[7];
            float cz = M[8]*pt[0] + M[9]*pt[1] + M[10]*pt[2] + M[11];
            float zc = fmaxf(cz, 1e-5f);
            float u  = cx / zc / 1408.0f;
            float v  = cy / zc / 512.0f;
            bool valid = (cz > 1e-5f) && (u > 0.0f) && (u < 1.0f)
                                      && (v > 0.0f) && (v < 1.0f);
            if (valid) mask |= (1 << n);
            suv[sgp * NCAM + n] = valid ? make_float2(u, v)
                                        : make_float2(-1.0f, -1.0f);
        }
        g_mask[(q0 + qi) * 32 + gp] = mask;
    }
    __syncthreads();

    // ---- descriptor emission: 768 tasks = (qi, cam, gp), 3 per thread ----
    const int Wl[4]  = {176, 88, 44, 22};
    const int Hl[4]  = {64, 32, 16, 8};
    const int HWl[4] = {11264, 2816, 704, 176};
    const int LB[4]  = {0, 17301504, 21626880, 22708224};

    #pragma unroll
    for (int k = 0; k < 3; ++k) {
        int tau = t + (k << 8);          // 0..767
        int qi  = tau / 192;
        int r   = tau - qi * 192;
        int cam = r >> 5, gp = r & 31;
        int sgp = qi * 32 + gp;
        float2 uv = suv[sgp * NCAM + cam];
        if (uv.x < 0.0f) continue;
        int idx = (q0 + qi) * 32 + gp;
        float4* dst = g_desc + (size_t)(idx * NCAM + cam) * (NL * 2);

        #pragma unroll
        for (int l = 0; l < NL; ++l) {
            int W = Wl[l], H = Hl[l];
            float x = uv.x * (float)W - 0.5f;
            float y = uv.y * (float)H - 0.5f;
            float xf = floorf(x), yf = floorf(y);
            float wx = x - xf,    wy = y - yf;
            int x0 = (int)xf, y0 = (int)yf;
            int x0c = max(x0, 0);
            int x1c = min(x0 + 1, W - 1);
            int y0c = max(y0, 0);
            int y1c = min(y0 + 1, H - 1);
            float a = (x0 >= 0)     ? (1.0f - wx) : 0.0f;
            float b = (x0 + 1 <= W - 1) ? wx      : 0.0f;
            float c = (y0 >= 0)     ? (1.0f - wy) : 0.0f;
            float d = (y0 + 1 <= H - 1) ? wy      : 0.0f;
            float swl = ssw[sgp * 4 + l];
            float4 wv = make_float4(a*c*swl, b*c*swl, a*d*swl, b*d*swl);
            int base = LB[l] + cam * HWl[l] * CCH + (y0c * W + x0c) * CCH;
            int dx   = (x1c - x0c) * CCH;
            int dy   = (y1c - y0c) * W * CCH;
            float4 md = make_float4(__int_as_float(base), __int_as_float(dx),
                                    __int_as_float(dy), 0.0f);
            dst[l*2 + 0] = wv;
            dst[l*2 + 1] = md;
        }
    }
}

__global__ __launch_bounds__(256) void fused_tp_prep_kernel(
    const float* __restrict__ f0, const float* __restrict__ f1,
    const float* __restrict__ f2, const float* __restrict__ f3,
    const float* __restrict__ query, const float* __restrict__ refpts,
    const float* __restrict__ l2i,
    const float* __restrict__ w_off, const float* __restrict__ b_off,
    const float* __restrict__ w_sw,  const float* __restrict__ b_sw)
{
    __shared__ unsigned int tile[64][128];   // 32 KB, reused by both paths

    int bid = blockIdx.x;
    if (bid < PREP_BLOCKS) {
        do_prep(bid, (float*)tile, query, refpts, l2i, w_off, b_off, w_sw, b_sw);
    } else {
        do_transpose(bid - PREP_BLOCKS, tile, f0, f1, f2, f3);
    }
}

// ---------------------------------------------------------------------------
// Kernel 2: lean gather. Warp = one (q,g,p); lane = 2 channels.
// Per valid cam: 4 levels x (2 broadcast desc loads + 4 half2 loads + 8 FFMA).
// ---------------------------------------------------------------------------
__global__ __launch_bounds__(256) void gather_kernel(float* __restrict__ out)
{
    const int qg = blockIdx.x;          // 0..9999
    const int q  = qg >> 2, g = qg & 3;
    const int t  = threadIdx.x;
    const int p  = t >> 5, lane = t & 31;
    const int gp = (g << 3) | p;
    const int idx = q * 32 + gp;
    const int gc  = (g << 6) | (lane << 1);   // channel in [0,256), even

    int mask = g_mask[idx];
    float2 acc = {0.f, 0.f};

    while (mask) {
        int n = __ffs(mask) - 1;
        mask &= mask - 1;
        const float4* dp = g_desc + (size_t)(idx * NCAM + n) * (NL * 2);
        #pragma unroll
        for (int l = 0; l < NL; ++l) {
            float4 wv = dp[l*2 + 0];
            float4 md = dp[l*2 + 1];
            int b  = __float_as_int(md.x) + gc;
            int dx = __float_as_int(md.y);
            int dy = __float_as_int(md.z);
            float2 v00 = __half22float2(*(const __half2*)(g_featT + b));
            float2 v10 = __half22float2(*(const __half2*)(g_featT + b + dx));
            float2 v01 = __half22float2(*(const __half2*)(g_featT + b + dy));
            float2 v11 = __half22float2(*(const __half2*)(g_featT + b + dx + dy));
            acc.x += wv.x*v00.x + wv.y*v10.x + wv.z*v01.x + wv.w*v11.x;
            acc.y += wv.x*v00.y + wv.y*v10.y + wv.z*v01.y + wv.w*v11.y;
        }
    }
    // out layout [B,Q,G,P,CG]: (idx)*64 + cg
    *(float2*)(out + (size_t)idx * CG + (lane << 1)) = acc;
}

// ---------------------------------------------------------------------------
extern "C" void kernel_launch(void* const* d_in, const int* in_sizes, int n_in,
                              void* d_out, int out_size)
{
    const float* query  = (const float*)d_in[0];
    const float* refpts = (const float*)d_in[1];
    const float* l2i    = (const float*)d_in[2];
    const float* w_off  = (const float*)d_in[3];
    const float* b_off  = (const float*)d_in[4];
    const float* w_sw   = (const float*)d_in[5];
    const float* b_sw   = (const float*)d_in[6];
    const float* f0     = (const float*)d_in[7];
    const float* f1     = (const float*)d_in[8];
    const float* f2     = (const float*)d_in[9];
    const float* f3     = (const float*)d_in[10];
    float* out = (float*)d_out;

    fused_tp_prep_kernel<<<TOTAL_BLOCKS, 256>>>(f0, f1, f2, f3,
        query, refpts, l2i, w_off, b_off, w_sw, b_sw);
    gather_kernel<<<10000, 256>>>(out);
}